// round 13
// baseline (speedup 1.0000x reference)
#include <cuda_runtime.h>
#include <math.h>

// Problem constants (fixed by setup_inputs)
#define BB 128
#define TT 32
#define HH 128
#define NNEI 16
#define NHEAD 4
#define LL 544                      // (NNEI+1)*TT
#define CH 8                        // l-chunks
#define CL 68                       // l per chunk (LL/CH)
#define NPAIR 34                    // l-pairs per chunk (CL/2)
#define SCALE 0.08838834764831845f  // 1/sqrt(128)

// Scratch (device globals — no allocations allowed)
__device__ float g_m[NHEAD * BB * HH];      // m[n][b][h]
__device__ float g_W2[NHEAD * HH * HH];     // W2[i][e]
__device__ float g_S[BB * NHEAD * LL];      // S[b][n][l] (masked, scaled)
__device__ float g_upart[CH * BB * 512];    // u partials per chunk
__device__ int   g_cnt[BB];                 // finalize counter (zero-init; reset by finalizer)
__device__ int   g_fHigh[4];                // mask-dtype detection votes
__device__ int   g_fMulti[4];

__device__ __forceinline__ float warpRedSum(float v) {
    v += __shfl_xor_sync(0xffffffffu, v, 16);
    v += __shfl_xor_sync(0xffffffffu, v, 8);
    v += __shfl_xor_sync(0xffffffffu, v, 4);
    v += __shfl_xor_sync(0xffffffffu, v, 2);
    v += __shfl_xor_sync(0xffffffffu, v, 1);
    return v;
}
__device__ __forceinline__ float warpRedMax(float v) {
    v = fmaxf(v, __shfl_xor_sync(0xffffffffu, v, 16));
    v = fmaxf(v, __shfl_xor_sync(0xffffffffu, v, 8));
    v = fmaxf(v, __shfl_xor_sync(0xffffffffu, v, 4));
    v = fmaxf(v, __shfl_xor_sync(0xffffffffu, v, 2));
    v = fmaxf(v, __shfl_xor_sync(0xffffffffu, v, 1));
    return v;
}

__device__ __forceinline__ int mask_mode() {
    return (g_fHigh[0] | g_fHigh[1] | g_fHigh[2] | g_fHigh[3]) ? 2
         : ((g_fMulti[0] | g_fMulti[1] | g_fMulti[2] | g_fMulti[3]) ? 1 : 0);
}

// ---------------------------------------------------------------------------
// Kernel 1: prep (196 blocks x 256 threads) — fully coalesced loads.
//   blocks [0,128):   m[n][b][h] for b = blockIdx.x (all 4 heads)
//   blocks [128,192): W2 fold via padded-smem tiled GEMM (n = j>>4, 8 h rows)
//   blocks [192,196): mask dtype detection (per-quarter vote slots)
// ---------------------------------------------------------------------------
__global__ __launch_bounds__(256) void prep_kernel(
    const float* __restrict__ node,   // [B,T,H]
    const float* __restrict__ wqs,    // [NH,H,H]
    const float* __restrict__ wks,    // [NH,H,H]
    const float* __restrict__ wvs,    // [NH,H,H]
    const float* __restrict__ prjw,   // [H, NH*H]
    const unsigned int* __restrict__ maskw,
    const int*   __restrict__ stepp)
{
    const int tid = threadIdx.x;
    const int lane = tid & 31;
    const int wid = tid >> 5;

    if (blockIdx.x < 128) {
        // ---- part A: m[n][b][h] for this b ----
        __shared__ float q_sm[128];
        __shared__ float qs_sm[4 * 128];
        const int b = blockIdx.x;
        const int ts = stepp[0];

        if (tid < 128)
            q_sm[tid] = node[(size_t)b * (TT * HH) + (size_t)ts * HH + tid];
        __syncthreads();

        // stage 1: q_s[n][d] = sum_h q[h] * wqs[n][h][d]; thread covers
        // (n0, d) and (n0+2, d) — coalesced (consecutive tid -> consecutive d)
        {
            const int d = tid & 127, n0 = tid >> 7;   // n0 in {0,1}
            float a0 = 0.f, a1 = 0.f;
            const float* w0 = wqs + (size_t)n0 * HH * HH + d;
            const float* w1 = wqs + (size_t)(n0 + 2) * HH * HH + d;
            #pragma unroll 8
            for (int h = 0; h < 128; h++) {
                float qv = q_sm[h];
                a0 += qv * w0[h * 128];
                a1 += qv * w1[h * 128];
            }
            qs_sm[n0 * 128 + d] = a0;
            qs_sm[(n0 + 2) * 128 + d] = a1;
        }
        __syncthreads();

        // stage 2: m[n][h] = dot(qs[n], wks[n][h]); warp handles a row PAIR:
        // lanes 0-15 -> row 2p, lanes 16-31 -> row 2p+1; each half-lane j
        // covers d = {4j..4j+3} and {64+4j..64+4j+3}. Loads are two 256B
        // contiguous segments per warp — coalesced.
        {
            const int half = lane >> 4;
            const int j = lane & 15;
            for (int p = wid; p < 256; p += 8) {
                int r = p * 2 + half;          // row index 0..511
                int n = r >> 7, h = r & 127;
                const float* wkr = wks + (size_t)n * HH * HH + (size_t)h * 128;
                float4 wa = *reinterpret_cast<const float4*>(wkr + j * 4);
                float4 wb = *reinterpret_cast<const float4*>(wkr + 64 + j * 4);
                float4 qa = *reinterpret_cast<const float4*>(qs_sm + n * 128 + j * 4);
                float4 qb = *reinterpret_cast<const float4*>(qs_sm + n * 128 + 64 + j * 4);
                float s = wa.x*qa.x + wa.y*qa.y + wa.z*qa.z + wa.w*qa.w
                        + wb.x*qb.x + wb.y*qb.y + wb.z*qb.z + wb.w*qb.w;
                // reduce within each 16-lane half
                s += __shfl_xor_sync(0xffffffffu, s, 1);
                s += __shfl_xor_sync(0xffffffffu, s, 2);
                s += __shfl_xor_sync(0xffffffffu, s, 4);
                s += __shfl_xor_sync(0xffffffffu, s, 8);
                if (j == 0)
                    g_m[((size_t)n * 128 + b) * 128 + h] = s;
            }
        }
    } else if (blockIdx.x < 192) {
        // ---- part B: W2[n*128+h][e] = sum_d wvs[n][h][d]*prjw[e][n*128+d]
        // Tiled GEMM through padded smem; all global loads coalesced.
        __shared__ float wv_sm[8 * 132];    // 8 rows, pad 132 (16B-aligned rows)
        __shared__ float p_sm[32 * 132];    // 32 e-rows, pad 132
        const int jb = blockIdx.x - 128;
        const int n  = jb >> 4;
        const int h0 = (jb & 15) * 8;

        // load 8 wv rows (coalesced linear)
        for (int i = tid; i < 8 * 128; i += 256) {
            int k = i >> 7, d = i & 127;
            wv_sm[k * 132 + d] = wvs[(size_t)n * HH * HH + (size_t)(h0 + k) * 128 + d];
        }

        const int e_l = tid >> 3;   // 0..31
        const int k   = tid & 7;    // 0..7
        const float4* wv4 = reinterpret_cast<const float4*>(wv_sm + k * 132);

        #pragma unroll 1
        for (int ec = 0; ec < 4; ec++) {
            __syncthreads();
            // stage 32 e-rows of the prjw slice (coalesced: consecutive tid ->
            // consecutive d within a row)
            for (int i = tid; i < 32 * 128; i += 256) {
                int e = i >> 7, d = i & 127;
                p_sm[e * 132 + d] = prjw[(size_t)(ec * 32 + e) * (NHEAD * HH) + n * 128 + d];
            }
            __syncthreads();

            const float4* pe4 = reinterpret_cast<const float4*>(p_sm + e_l * 132);
            float a = 0.f;
            #pragma unroll 8
            for (int d4 = 0; d4 < 32; d4++) {
                float4 w = wv4[d4];
                float4 p = pe4[d4];
                a += w.x*p.x + w.y*p.y + w.z*p.z + w.w*p.w;
            }
            g_W2[((size_t)n * 128 + h0 + k) * 128 + (ec * 32 + e_l)] = a;
        }
    } else {
        __shared__ int sH, sM;
        if (tid == 0) { sH = 0; sM = 0; }
        __syncthreads();
        const int q = blockIdx.x - 192;
        const int QW = (BB * LL / 4) / 4;   // 4352 words per quarter
        const unsigned int* p = maskw + q * QW;
        int lh = 0, lm = 0;
        #pragma unroll 4
        for (int i = tid; i < QW; i += 256) {
            unsigned int w = p[i];
            unsigned int b0 = w & 0xFFu, b1 = (w >> 8) & 0xFFu,
                         b2 = (w >> 16) & 0xFFu, b3 = (w >> 24) & 0xFFu;
            if (b0 > 1u || b1 > 1u || b2 > 1u || b3 > 1u) lh = 1;
            if ((w & 0xFFFFFF00u) != 0u) lm = 1;
        }
        if (lh) atomicOr(&sH, 1);
        if (lm) atomicOr(&sM, 1);
        __syncthreads();
        if (tid == 0) { g_fHigh[q] = sH; g_fMulti[q] = sM; }
    }
}

// ---------------------------------------------------------------------------
// Kernel 2: scores. grid (128 b, 8 c) x 256 threads.
// Each warp processes l-PAIRS: lanes 0-15 handle l0, lanes 16-31 handle l0+1.
// ---------------------------------------------------------------------------
__global__ __launch_bounds__(256) void score_kernel(
    const float* __restrict__ node,    // [B,T,H]
    const float* __restrict__ neigh,   // [B,N*T,H]
    const void*  __restrict__ maskraw)
{
    __shared__ float m_sm[NHEAD * HH];
    const int tid = threadIdx.x;
    const int b = blockIdx.x;
    const int c = blockIdx.y;
    const int lane = tid & 31;
    const int wid = tid >> 5;
    const int j = lane & 15;            // position within 16-lane half
    const float NEG_INF = __int_as_float(0xff800000u);
    const int mode = mask_mode();

    m_sm[tid]       = g_m[((size_t)(tid >> 7) * 128 + b) * 128 + (tid & 127)];
    m_sm[tid + 256] = g_m[((size_t)((tid + 256) >> 7) * 128 + b) * 128 + ((tid + 256) & 127)];
    __syncthreads();

    // lane's h-coverage: h = 4j (lo float4) and 4j+64 (hi float4), per head
    const float4* m4 = reinterpret_cast<const float4*>(m_sm);
    float4 mA[4], mB[4];
    #pragma unroll
    for (int n = 0; n < 4; n++) {
        mA[n] = m4[n * 32 + j];
        mB[n] = m4[n * 32 + 16 + j];
    }

    const float4* nodeB  = reinterpret_cast<const float4*>(node  + (size_t)b * TT * HH);
    const float4* neighB = reinterpret_cast<const float4*>(neigh + (size_t)b * NNEI * TT * HH);
    const int half = lane >> 4;

    for (int p = wid; p < NPAIR; p += 8) {
        int l = c * CL + 2 * p + half;   // per-lane l (halves differ)
        const float4* row = (l < TT) ? (nodeB + (size_t)l * 32) : (neighB + (size_t)(l - TT) * 32);
        float4 vA = row[j];
        float4 vB = row[j + 16];
        float s0 = vA.x*mA[0].x + vA.y*mA[0].y + vA.z*mA[0].z + vA.w*mA[0].w
                 + vB.x*mB[0].x + vB.y*mB[0].y + vB.z*mB[0].z + vB.w*mB[0].w;
        float s1 = vA.x*mA[1].x + vA.y*mA[1].y + vA.z*mA[1].z + vA.w*mA[1].w
                 + vB.x*mB[1].x + vB.y*mB[1].y + vB.z*mB[1].z + vB.w*mB[1].w;
        float s2 = vA.x*mA[2].x + vA.y*mA[2].y + vA.z*mA[2].z + vA.w*mA[2].w
                 + vB.x*mB[2].x + vB.y*mB[2].y + vB.z*mB[2].z + vB.w*mB[2].w;
        float s3 = vA.x*mA[3].x + vA.y*mA[3].y + vA.z*mA[3].z + vA.w*mA[3].w
                 + vB.x*mB[3].x + vB.y*mB[3].y + vB.z*mB[3].z + vB.w*mB[3].w;
        s0 += __shfl_xor_sync(0xffffffffu, s0, 1);  s0 += __shfl_xor_sync(0xffffffffu, s0, 2);
        s1 += __shfl_xor_sync(0xffffffffu, s1, 1);  s1 += __shfl_xor_sync(0xffffffffu, s1, 2);
        s2 += __shfl_xor_sync(0xffffffffu, s2, 1);  s2 += __shfl_xor_sync(0xffffffffu, s2, 2);
        s3 += __shfl_xor_sync(0xffffffffu, s3, 1);  s3 += __shfl_xor_sync(0xffffffffu, s3, 2);
        int q = lane & 3;
        float w = (q == 0) ? s0 : (q == 1) ? s1 : (q == 2) ? s2 : s3;
        w += __shfl_xor_sync(0xffffffffu, w, 4);
        w += __shfl_xor_sync(0xffffffffu, w, 8);
        if ((lane & 12) == 0) {  // lanes 0-3 (l0) and 16-19 (l1)
            size_t mi = (size_t)b * LL + l;
            bool mk;
            if (mode == 0)      mk = (reinterpret_cast<const int*>(maskraw)[mi] != 0);
            else if (mode == 1) mk = (reinterpret_cast<const unsigned char*>(maskraw)[mi] != 0);
            else                mk = (reinterpret_cast<const float*>(maskraw)[mi] != 0.f);
            g_S[((size_t)b * NHEAD + q) * LL + l] = mk ? NEG_INF : w * SCALE;
        }
    }
}

// ---------------------------------------------------------------------------
// Kernel 3: ctx. grid (128 b, 8 c) x 256 threads. Softmax (redundant per
// block), slf_attn chunk, weighted sum over own chunk, u-partials; LAST
// block per b finalizes (u sum, proj = u@W2, residual + LayerNorm).
// ---------------------------------------------------------------------------
__global__ __launch_bounds__(256) void ctx_kernel(
    const float* __restrict__ node,
    const float* __restrict__ neigh,
    const float* __restrict__ prjb,
    const float* __restrict__ gamma,
    const float* __restrict__ beta,
    const int*   __restrict__ stepp,
    float* __restrict__ outp)
{
    __shared__ float SA[NHEAD * LL];        // 8.5 KB (probs; reused as u_sm)
    __shared__ float part[8 * NHEAD * HH];  // 16 KB
    __shared__ float red[8];
    __shared__ float red2[8];
    __shared__ int   isLast;

    const int tid = threadIdx.x;
    const int b = blockIdx.x;
    const int c = blockIdx.y;
    const int lane = tid & 31;
    const int wid = tid >> 5;
    const int j = lane & 15;
    const int half = lane >> 4;
    const float NEG_INF = __int_as_float(0xff800000u);

    // load S[b]
    {
        const float4* Sg = reinterpret_cast<const float4*>(g_S + (size_t)b * NHEAD * LL);
        float4* SA4 = reinterpret_cast<float4*>(SA);
        for (int i = tid; i < NHEAD * LL / 4; i += 256) SA4[i] = Sg[i];
    }
    __syncthreads();

    // softmax: 2 warps per head
    {
        const int n = wid >> 1;
        const int hh = wid & 1;
        float mx = NEG_INF;
        for (int l = hh * 32 + lane; l < LL; l += 64) mx = fmaxf(mx, SA[n * LL + l]);
        mx = warpRedMax(mx);
        if (lane == 0) red[wid] = mx;
        __syncthreads();
        mx = fmaxf(red[n * 2], red[n * 2 + 1]);

        float sm = 0.f;
        for (int l = hh * 32 + lane; l < LL; l += 64) {
            float e = __expf(SA[n * LL + l] - mx);
            SA[n * LL + l] = e;
            sm += e;
        }
        sm = warpRedSum(sm);
        if (lane == 0) red2[wid] = sm;
        __syncthreads();
        float inv = 1.f / (red2[n * 2] + red2[n * 2 + 1]);
        for (int l = hh * 32 + lane; l < LL; l += 64) SA[n * LL + l] *= inv;
    }
    __syncthreads();

    // slf_attn for own chunk
    if (tid < CL) {
        int l = c * CL + tid;
        outp[BB * HH + (size_t)b * LL + l] = SA[l] + SA[LL + l] + SA[2 * LL + l] + SA[3 * LL + l];
    }

    // weighted sum over own chunk, l-pair scheme
    const float4* nodeB  = reinterpret_cast<const float4*>(node  + (size_t)b * TT * HH);
    const float4* neighB = reinterpret_cast<const float4*>(neigh + (size_t)b * NNEI * TT * HH);
    {
        float4 aLo[4], aHi[4];
        #pragma unroll
        for (int n = 0; n < 4; n++) { aLo[n] = make_float4(0,0,0,0); aHi[n] = make_float4(0,0,0,0); }

        for (int p = wid; p < NPAIR; p += 8) {
            int l = c * CL + 2 * p + half;
            const float4* row = (l < TT) ? (nodeB + (size_t)l * 32) : (neighB + (size_t)(l - TT) * 32);
            float4 vA = row[j];
            float4 vB = row[j + 16];
            float c0 = SA[l], c1 = SA[LL + l], c2 = SA[2 * LL + l], c3 = SA[3 * LL + l];
            aLo[0].x += c0*vA.x; aLo[0].y += c0*vA.y; aLo[0].z += c0*vA.z; aLo[0].w += c0*vA.w;
            aHi[0].x += c0*vB.x; aHi[0].y += c0*vB.y; aHi[0].z += c0*vB.z; aHi[0].w += c0*vB.w;
            aLo[1].x += c1*vA.x; aLo[1].y += c1*vA.y; aLo[1].z += c1*vA.z; aLo[1].w += c1*vA.w;
            aHi[1].x += c1*vB.x; aHi[1].y += c1*vB.y; aHi[1].z += c1*vB.z; aHi[1].w += c1*vB.w;
            aLo[2].x += c2*vA.x; aLo[2].y += c2*vA.y; aLo[2].z += c2*vA.z; aLo[2].w += c2*vA.w;
            aHi[2].x += c2*vB.x; aHi[2].y += c2*vB.y; aHi[2].z += c2*vB.z; aHi[2].w += c2*vB.w;
            aLo[3].x += c3*vA.x; aLo[3].y += c3*vA.y; aLo[3].z += c3*vA.z; aLo[3].w += c3*vA.w;
            aHi[3].x += c3*vB.x; aHi[3].y += c3*vB.y; aHi[3].z += c3*vB.z; aHi[3].w += c3*vB.w;
        }
        #pragma unroll
        for (int n = 0; n < 4; n++) {
            aLo[n].x += __shfl_xor_sync(0xffffffffu, aLo[n].x, 16);
            aLo[n].y += __shfl_xor_sync(0xffffffffu, aLo[n].y, 16);
            aLo[n].z += __shfl_xor_sync(0xffffffffu, aLo[n].z, 16);
            aLo[n].w += __shfl_xor_sync(0xffffffffu, aLo[n].w, 16);
            aHi[n].x += __shfl_xor_sync(0xffffffffu, aHi[n].x, 16);
            aHi[n].y += __shfl_xor_sync(0xffffffffu, aHi[n].y, 16);
            aHi[n].z += __shfl_xor_sync(0xffffffffu, aHi[n].z, 16);
            aHi[n].w += __shfl_xor_sync(0xffffffffu, aHi[n].w, 16);
        }
        if (half == 0) {
            float4* P = reinterpret_cast<float4*>(part);
            #pragma unroll
            for (int n = 0; n < 4; n++) {
                P[(wid * 4 + n) * 32 + j]      = aLo[n];   // h = 4j
                P[(wid * 4 + n) * 32 + 16 + j] = aHi[n];   // h = 4j+64
            }
        }
    }
    __syncthreads();
    {
        #pragma unroll
        for (int r = 0; r < 2; r++) {
            int idx = tid + r * 256;
            int n = idx >> 7, h = idx & 127;
            float u = 0.f;
            #pragma unroll
            for (int g = 0; g < 8; g++) u += part[(g * 4 + n) * 128 + h];
            g_upart[((size_t)c * BB + b) * 512 + idx] = u;
        }
    }

    // ---- last block per b finalizes (no spinning) ----
    __threadfence();
    __syncthreads();
    if (tid == 0) isLast = (atomicAdd(&g_cnt[b], 1) == CH - 1);
    __syncthreads();
    if (!isLast) return;
    __threadfence();

    float* u_sm = SA;  // reuse
    #pragma unroll
    for (int r = 0; r < 2; r++) {
        int idx = tid + r * 256;
        float u = 0.f;
        #pragma unroll
        for (int cc = 0; cc < CH; cc++)
            u += g_upart[((size_t)cc * BB + b) * 512 + idx];
        u_sm[idx] = u;
    }
    __syncthreads();

    // projection: warp wid handles i in [wid*64, wid*64+64); lane owns float4 of e
    {
        const float4* W24 = reinterpret_cast<const float4*>(g_W2);
        float4 acc = make_float4(0, 0, 0, 0);
        const int i0 = wid * 64;
        #pragma unroll 8
        for (int k = 0; k < 64; k++) {
            int i = i0 + k;
            float uv = u_sm[i];
            float4 wv = W24[(size_t)i * 32 + lane];
            acc.x += uv * wv.x; acc.y += uv * wv.y; acc.z += uv * wv.z; acc.w += uv * wv.w;
        }
        reinterpret_cast<float4*>(part)[wid * 32 + lane] = acc;  // part[wid*128+e]
    }
    __syncthreads();

    {
        const int ts = stepp[0];
        float x = 0.f;
        if (tid < 128) {
            float p = 0.f;
            #pragma unroll
            for (int w = 0; w < 8; w++) p += part[w * 128 + tid];
            x = p + prjb[tid] + node[(size_t)b * (TT * HH) + (size_t)ts * HH + tid];
        }
        float ws = warpRedSum(x);
        if (tid < 128 && lane == 0) red[wid] = ws;
        __syncthreads();
        float mean = (red[0] + red[1] + red[2] + red[3]) * (1.f / 128.f);
        float d = x - mean;
        float wq = warpRedSum(d * d);
        if (tid < 128 && lane == 0) red2[wid] = wq;
        __syncthreads();
        if (tid < 128) {
            float var = (red2[0] + red2[1] + red2[2] + red2[3]) * (1.f / 128.f);
            outp[(size_t)b * 128 + tid] = d * rsqrtf(var + 1e-6f) * gamma[tid] + beta[tid];
        }
        if (tid == 0) g_cnt[b] = 0;   // reset for next graph replay
    }
}

extern "C" void kernel_launch(void* const* d_in, const int* in_sizes, int n_in,
                              void* d_out, int out_size)
{
    const float* node  = (const float*)d_in[0];
    const float* neigh = (const float*)d_in[1];
    const void*  mask  = d_in[2];
    const int*   step  = (const int*)d_in[3];
    const float* wqs   = (const float*)d_in[4];
    const float* wks   = (const float*)d_in[5];
    const float* wvs   = (const float*)d_in[6];
    const float* prjw  = (const float*)d_in[7];
    const float* prjb  = (const float*)d_in[8];
    const float* gamma = (const float*)d_in[9];
    const float* beta  = (const float*)d_in[10];
    float* outp = (float*)d_out;

    prep_kernel<<<196, 256>>>(node, wqs, wks, wvs, prjw,
                              (const unsigned int*)mask, step);
    score_kernel<<<dim3(128, CH), 256>>>(node, neigh, mask);
    ctx_kernel<<<dim3(128, CH), 256>>>(node, neigh, prjb, gamma, beta, step, outp);
}

// round 14
// speedup vs baseline: 1.1964x; 1.1964x over previous
#include <cuda_runtime.h>
#include <math.h>

// Problem constants (fixed by setup_inputs)
#define BB 128
#define TT 32
#define HH 128
#define NNEI 16
#define NHEAD 4
#define LL 544                      // (NNEI+1)*TT
#define CH 8                        // l-chunks
#define CL 68                       // l per chunk (LL/CH)
#define NPAIR 34                    // l-pairs per chunk (CL/2)
#define SCALE 0.08838834764831845f  // 1/sqrt(128)

// Scratch (device globals — no allocations allowed)
__device__ float  g_m[NHEAD * BB * HH];     // m[n][b][h]
__device__ float  g_W2[NHEAD * HH * HH];    // W2[i][e]
__device__ float  g_S[BB * NHEAD * LL];     // raw masked/scaled scores
__device__ float  g_upart[CH * BB * 512];   // chunk u partials (exp-numerator weighted)
__device__ float2 g_MZ[CH * BB * NHEAD];    // chunk (max, sum)
__device__ int    g_cnt[BB];                // finalize counter (zero-init; reset by finalizer)
__device__ int    g_fHigh[4];               // mask-dtype detection votes
__device__ int    g_fMulti[4];

__device__ __forceinline__ float warpRedSum(float v) {
    v += __shfl_xor_sync(0xffffffffu, v, 16);
    v += __shfl_xor_sync(0xffffffffu, v, 8);
    v += __shfl_xor_sync(0xffffffffu, v, 4);
    v += __shfl_xor_sync(0xffffffffu, v, 2);
    v += __shfl_xor_sync(0xffffffffu, v, 1);
    return v;
}
__device__ __forceinline__ float warpRedMax(float v) {
    v = fmaxf(v, __shfl_xor_sync(0xffffffffu, v, 16));
    v = fmaxf(v, __shfl_xor_sync(0xffffffffu, v, 8));
    v = fmaxf(v, __shfl_xor_sync(0xffffffffu, v, 4));
    v = fmaxf(v, __shfl_xor_sync(0xffffffffu, v, 2));
    v = fmaxf(v, __shfl_xor_sync(0xffffffffu, v, 1));
    return v;
}

__device__ __forceinline__ int mask_mode() {
    return (g_fHigh[0] | g_fHigh[1] | g_fHigh[2] | g_fHigh[3]) ? 2
         : ((g_fMulti[0] | g_fMulti[1] | g_fMulti[2] | g_fMulti[3]) ? 1 : 0);
}

// ---------------------------------------------------------------------------
// Kernel 1: prep (132 blocks x 256 threads)
//   blocks [0,64):    m[n][b][h], n = blk>>4, 8 batches per block (8MB traffic)
//   blocks [64,128):  W2 fold via padded-smem tiled GEMM
//   blocks [128,132): mask dtype detection
// ---------------------------------------------------------------------------
__global__ __launch_bounds__(256) void prep_kernel(
    const float* __restrict__ node,   // [B,T,H]
    const float* __restrict__ wqs,    // [NH,H,H]
    const float* __restrict__ wks,    // [NH,H,H]
    const float* __restrict__ wvs,    // [NH,H,H]
    const float* __restrict__ prjw,   // [H, NH*H]
    const unsigned int* __restrict__ maskw,
    const int*   __restrict__ stepp)
{
    const int tid = threadIdx.x;
    const int lane = tid & 31;
    const int wid = tid >> 5;

    if (blockIdx.x < 64) {
        // ---- m[n][b][h] for 8 batches ----
        __shared__ float q_sm[8 * 128];
        __shared__ float qs_sm[8 * 128];
        const int n  = blockIdx.x >> 4;
        const int b0 = (blockIdx.x & 15) * 8;
        const int ts = stepp[0];

        for (int i = tid; i < 8 * 128; i += 256) {
            int b = i >> 7, h = i & 127;
            q_sm[i] = node[(size_t)(b0 + b) * (TT * HH) + (size_t)ts * HH + h];
        }
        __syncthreads();

        // stage 1: qs[b][d] = sum_h q[b][h]*wqs[n][h][d]
        // thread: d = tid&127, half = tid>>7 covers b in {half*4 .. half*4+4)
        {
            const int d = tid & 127;
            const int bh = (tid >> 7) * 4;
            float a0 = 0.f, a1 = 0.f, a2 = 0.f, a3 = 0.f;
            const float* wq = wqs + (size_t)n * HH * HH + d;
            #pragma unroll 8
            for (int h = 0; h < 128; h++) {
                float w = wq[h * 128];                 // coalesced across tid
                a0 += q_sm[(bh + 0) * 128 + h] * w;    // smem broadcasts
                a1 += q_sm[(bh + 1) * 128 + h] * w;
                a2 += q_sm[(bh + 2) * 128 + h] * w;
                a3 += q_sm[(bh + 3) * 128 + h] * w;
            }
            qs_sm[(bh + 0) * 128 + d] = a0;
            qs_sm[(bh + 1) * 128 + d] = a1;
            qs_sm[(bh + 2) * 128 + d] = a2;
            qs_sm[(bh + 3) * 128 + d] = a3;
        }
        __syncthreads();

        // stage 2: m[b][h] = dot(qs[b], wks[n][h]); warp handles h-row pairs
        // (lanes 0-15 -> row 2p, 16-31 -> 2p+1), coalesced 256B row loads.
        {
            const int half = lane >> 4;
            const int j = lane & 15;
            #pragma unroll 1
            for (int p = wid; p < 64; p += 8) {
                int h = p * 2 + half;
                const float* wkr = wks + (size_t)n * HH * HH + (size_t)h * 128;
                float4 wa = *reinterpret_cast<const float4*>(wkr + j * 4);
                float4 wb = *reinterpret_cast<const float4*>(wkr + 64 + j * 4);
                #pragma unroll
                for (int bb = 0; bb < 8; bb++) {
                    float4 qa = *reinterpret_cast<const float4*>(qs_sm + bb * 128 + j * 4);
                    float4 qb = *reinterpret_cast<const float4*>(qs_sm + bb * 128 + 64 + j * 4);
                    float s = wa.x*qa.x + wa.y*qa.y + wa.z*qa.z + wa.w*qa.w
                            + wb.x*qb.x + wb.y*qb.y + wb.z*qb.z + wb.w*qb.w;
                    s += __shfl_xor_sync(0xffffffffu, s, 1);
                    s += __shfl_xor_sync(0xffffffffu, s, 2);
                    s += __shfl_xor_sync(0xffffffffu, s, 4);
                    s += __shfl_xor_sync(0xffffffffu, s, 8);
                    if (j == 0)
                        g_m[((size_t)n * 128 + b0 + bb) * 128 + h] = s;
                }
            }
        }
    } else if (blockIdx.x < 128) {
        // ---- W2[n*128+h][e] = sum_d wvs[n][h][d]*prjw[e][n*128+d] ----
        __shared__ float wv_sm[8 * 132];
        __shared__ float p_sm[32 * 132];
        const int jb = blockIdx.x - 64;
        const int n  = jb >> 4;
        const int h0 = (jb & 15) * 8;

        for (int i = tid; i < 8 * 128; i += 256) {
            int k = i >> 7, d = i & 127;
            wv_sm[k * 132 + d] = wvs[(size_t)n * HH * HH + (size_t)(h0 + k) * 128 + d];
        }

        const int e_l = tid >> 3;   // 0..31
        const int k   = tid & 7;    // 0..7
        const float4* wv4 = reinterpret_cast<const float4*>(wv_sm + k * 132);

        #pragma unroll 1
        for (int ec = 0; ec < 4; ec++) {
            __syncthreads();
            for (int i = tid; i < 32 * 128; i += 256) {
                int e = i >> 7, d = i & 127;
                p_sm[e * 132 + d] = prjw[(size_t)(ec * 32 + e) * (NHEAD * HH) + n * 128 + d];
            }
            __syncthreads();

            const float4* pe4 = reinterpret_cast<const float4*>(p_sm + e_l * 132);
            float a = 0.f;
            #pragma unroll 8
            for (int d4 = 0; d4 < 32; d4++) {
                float4 w = wv4[d4];
                float4 p = pe4[d4];
                a += w.x*p.x + w.y*p.y + w.z*p.z + w.w*p.w;
            }
            g_W2[((size_t)n * 128 + h0 + k) * 128 + (ec * 32 + e_l)] = a;
        }
    } else {
        __shared__ int sH, sM;
        if (tid == 0) { sH = 0; sM = 0; }
        __syncthreads();
        const int q = blockIdx.x - 128;
        const int QW = (BB * LL / 4) / 4;   // 4352 words per quarter
        const unsigned int* p = maskw + q * QW;
        int lh = 0, lm = 0;
        #pragma unroll 4
        for (int i = tid; i < QW; i += 256) {
            unsigned int w = p[i];
            unsigned int b0 = w & 0xFFu, b1 = (w >> 8) & 0xFFu,
                         b2 = (w >> 16) & 0xFFu, b3 = (w >> 24) & 0xFFu;
            if (b0 > 1u || b1 > 1u || b2 > 1u || b3 > 1u) lh = 1;
            if ((w & 0xFFFFFF00u) != 0u) lm = 1;
        }
        if (lh) atomicOr(&sH, 1);
        if (lm) atomicOr(&sM, 1);
        __syncthreads();
        if (tid == 0) { g_fHigh[q] = sH; g_fMulti[q] = sM; }
    }
}

// ---------------------------------------------------------------------------
// Kernel 2: mega2. grid (128 b, 8 c) x 256 threads. Single kv read:
//   1. stage kv chunk (68 rows) into smem
//   2. scores from smem (pair scheme) -> SS + g_S
//   3. chunk-local softmax (M_c, Z_c) -> exp numerators in SS, g_MZ
//   4. u-partials from smem kv -> g_upart
//   5. LAST block per b: combine chunks (flash rescale), proj=u@W2,
//      residual + LayerNorm, and slf_attn row from g_S with global (M,Z).
// ---------------------------------------------------------------------------
__global__ __launch_bounds__(256) void mega2_kernel(
    const float* __restrict__ node,    // [B,T,H]
    const float* __restrict__ neigh,   // [B,N*T,H]
    const void*  __restrict__ maskraw, // [B,L]
    const float* __restrict__ prjb,
    const float* __restrict__ gamma,
    const float* __restrict__ beta,
    const int*   __restrict__ stepp,
    float* __restrict__ outp)
{
    __shared__ float kv_sm[CL * 128];   // 34 KB (finalize reuses as u_sm/part)
    __shared__ float m_sm[NHEAD * HH];  // 2 KB
    __shared__ float SS[NHEAD * CL];    // scores -> exp numerators
    __shared__ float sCoef[NHEAD * CH]; // finalize: exp(Mc-M)/Z per chunk
    __shared__ float sMg[NHEAD];
    __shared__ float sZinv[NHEAD];
    __shared__ float red[8], red2[8];
    __shared__ int   isLast;

    const int tid = threadIdx.x;
    const int b = blockIdx.x;
    const int c = blockIdx.y;
    const int lane = tid & 31;
    const int wid = tid >> 5;
    const int j = lane & 15;
    const int half = lane >> 4;
    const float NEG_INF = __int_as_float(0xff800000u);
    const int l0 = c * CL;

    // m for this b
    m_sm[tid]       = g_m[((size_t)(tid >> 7) * 128 + b) * 128 + (tid & 127)];
    m_sm[tid + 256] = g_m[((size_t)((tid + 256) >> 7) * 128 + b) * 128 + ((tid + 256) & 127)];

    // stage kv chunk
    const float4* nodeB  = reinterpret_cast<const float4*>(node  + (size_t)b * TT * HH);
    const float4* neighB = reinterpret_cast<const float4*>(neigh + (size_t)b * NNEI * TT * HH);
    {
        float4* kv4 = reinterpret_cast<float4*>(kv_sm);
        for (int i = tid; i < CL * 32; i += 256) {
            int row = i >> 5, f4 = i & 31;
            int l = l0 + row;
            kv4[i] = (l < TT) ? nodeB[(size_t)l * 32 + f4] : neighB[(size_t)(l - TT) * 32 + f4];
        }
    }
    __syncthreads();

    // ---- scores from smem (pair scheme) ----
    {
        const int mode = mask_mode();
        const float4* m4 = reinterpret_cast<const float4*>(m_sm);
        float4 mA[4], mB[4];
        #pragma unroll
        for (int n = 0; n < 4; n++) {
            mA[n] = m4[n * 32 + j];
            mB[n] = m4[n * 32 + 16 + j];
        }
        const float4* kv4 = reinterpret_cast<const float4*>(kv_sm);
        for (int p = wid; p < NPAIR; p += 8) {
            int ll = 2 * p + half;   // local l
            float4 vA = kv4[ll * 32 + j];
            float4 vB = kv4[ll * 32 + 16 + j];
            float s0 = vA.x*mA[0].x + vA.y*mA[0].y + vA.z*mA[0].z + vA.w*mA[0].w
                     + vB.x*mB[0].x + vB.y*mB[0].y + vB.z*mB[0].z + vB.w*mB[0].w;
            float s1 = vA.x*mA[1].x + vA.y*mA[1].y + vA.z*mA[1].z + vA.w*mA[1].w
                     + vB.x*mB[1].x + vB.y*mB[1].y + vB.z*mB[1].z + vB.w*mB[1].w;
            float s2 = vA.x*mA[2].x + vA.y*mA[2].y + vA.z*mA[2].z + vA.w*mA[2].w
                     + vB.x*mB[2].x + vB.y*mB[2].y + vB.z*mB[2].z + vB.w*mB[2].w;
            float s3 = vA.x*mA[3].x + vA.y*mA[3].y + vA.z*mA[3].z + vA.w*mA[3].w
                     + vB.x*mB[3].x + vB.y*mB[3].y + vB.z*mB[3].z + vB.w*mB[3].w;
            s0 += __shfl_xor_sync(0xffffffffu, s0, 1);  s0 += __shfl_xor_sync(0xffffffffu, s0, 2);
            s1 += __shfl_xor_sync(0xffffffffu, s1, 1);  s1 += __shfl_xor_sync(0xffffffffu, s1, 2);
            s2 += __shfl_xor_sync(0xffffffffu, s2, 1);  s2 += __shfl_xor_sync(0xffffffffu, s2, 2);
            s3 += __shfl_xor_sync(0xffffffffu, s3, 1);  s3 += __shfl_xor_sync(0xffffffffu, s3, 2);
            int q = lane & 3;
            float w = (q == 0) ? s0 : (q == 1) ? s1 : (q == 2) ? s2 : s3;
            w += __shfl_xor_sync(0xffffffffu, w, 4);
            w += __shfl_xor_sync(0xffffffffu, w, 8);
            if ((lane & 12) == 0) {
                size_t mi = (size_t)b * LL + l0 + ll;
                bool mk;
                if (mode == 0)      mk = (reinterpret_cast<const int*>(maskraw)[mi] != 0);
                else if (mode == 1) mk = (reinterpret_cast<const unsigned char*>(maskraw)[mi] != 0);
                else                mk = (reinterpret_cast<const float*>(maskraw)[mi] != 0.f);
                float sv = mk ? NEG_INF : w * SCALE;
                SS[q * CL + ll] = sv;
                g_S[((size_t)b * NHEAD + q) * LL + l0 + ll] = sv;
            }
        }
    }
    __syncthreads();

    // ---- chunk softmax stats (warp n handles head n) ----
    if (wid < 4) {
        const int n = wid;
        float v0 = SS[n * CL + lane];
        float v1 = SS[n * CL + 32 + lane];
        float v2 = (lane < 4) ? SS[n * CL + 64 + lane] : NEG_INF;
        float M = warpRedMax(fmaxf(fmaxf(v0, v1), v2));
        float Mu = fmaxf(M, -1e30f);
        float e0 = __expf(v0 - Mu);
        float e1 = __expf(v1 - Mu);
        float e2 = (lane < 4) ? __expf(v2 - Mu) : 0.f;
        float Z = warpRedSum(e0 + e1 + e2);
        SS[n * CL + lane] = e0;
        SS[n * CL + 32 + lane] = e1;
        if (lane < 4) SS[n * CL + 64 + lane] = e2;
        if (lane == 0)
            g_MZ[((size_t)c * BB + b) * NHEAD + n] = make_float2(M, Z);
    }
    __syncthreads();

    // ---- u-partials: thread owns (n0, h) and (n0+2, h) ----
    {
        const int h = tid & 127;
        const int n0 = tid >> 7;          // 0 or 1
        float a0 = 0.f, a1 = 0.f;
        #pragma unroll 4
        for (int l = 0; l < CL; l++) {
            float kvv = kv_sm[l * 128 + h];
            a0 += SS[n0 * CL + l] * kvv;
            a1 += SS[(n0 + 2) * CL + l] * kvv;
        }
        g_upart[((size_t)c * BB + b) * 512 + n0 * 128 + h]       = a0;
        g_upart[((size_t)c * BB + b) * 512 + (n0 + 2) * 128 + h] = a1;
    }

    // ---- last block per b finalizes ----
    __threadfence();
    __syncthreads();
    if (tid == 0) isLast = (atomicAdd(&g_cnt[b], 1) == CH - 1);
    __syncthreads();
    if (!isLast) return;
    __threadfence();

    // combine chunk stats: warp n handles head n; lanes 0..7 = chunks
    if (wid < 4) {
        const int n = wid;
        float Mc = NEG_INF, Zc = 0.f;
        if (lane < CH) {
            float2 mz = g_MZ[((size_t)lane * BB + b) * NHEAD + n];
            Mc = mz.x; Zc = mz.y;
        }
        float M = warpRedMax(Mc);
        float wgt = (lane < CH) ? Zc * __expf(Mc - M) : 0.f;
        float Z = warpRedSum(wgt);
        if (lane < CH) sCoef[n * CH + lane] = __expf(Mc - M) / Z;
        if (lane == 0) { sMg[n] = M; sZinv[n] = 1.f / Z; }
    }
    __syncthreads();

    // u_sm (reuse kv_sm)
    float* u_sm = kv_sm;
    float* part = kv_sm + 512;
    #pragma unroll
    for (int r = 0; r < 2; r++) {
        int idx = tid + r * 256;
        int n = idx >> 7;
        float u = 0.f;
        #pragma unroll
        for (int cc = 0; cc < CH; cc++)
            u += g_upart[((size_t)cc * BB + b) * 512 + idx] * sCoef[n * CH + cc];
        u_sm[idx] = u;
    }
    __syncthreads();

    // projection: warp wid handles i in [wid*64, wid*64+64); lane owns float4 of e
    {
        const float4* W24 = reinterpret_cast<const float4*>(g_W2);
        float4 acc = make_float4(0, 0, 0, 0);
        const int i0 = wid * 64;
        #pragma unroll 8
        for (int k = 0; k < 64; k++) {
            int i = i0 + k;
            float uv = u_sm[i];
            float4 wv = W24[(size_t)i * 32 + lane];
            acc.x += uv * wv.x; acc.y += uv * wv.y; acc.z += uv * wv.z; acc.w += uv * wv.w;
        }
        reinterpret_cast<float4*>(part)[wid * 32 + lane] = acc;
    }
    __syncthreads();

    // residual + LayerNorm
    {
        const int ts = stepp[0];
        float x = 0.f;
        if (tid < 128) {
            float p = 0.f;
            #pragma unroll
            for (int w = 0; w < 8; w++) p += part[w * 128 + tid];
            x = p + prjb[tid] + node[(size_t)b * (TT * HH) + (size_t)ts * HH + tid];
        }
        float ws = warpRedSum(x);
        if (tid < 128 && lane == 0) red[wid] = ws;
        __syncthreads();
        float mean = (red[0] + red[1] + red[2] + red[3]) * (1.f / 128.f);
        float d = x - mean;
        float wq = warpRedSum(d * d);
        if (tid < 128 && lane == 0) red2[wid] = wq;
        __syncthreads();
        if (tid < 128) {
            float var = (red2[0] + red2[1] + red2[2] + red2[3]) * (1.f / 128.f);
            outp[(size_t)b * 128 + tid] = d * rsqrtf(var + 1e-6f) * gamma[tid] + beta[tid];
        }
    }

    // slf_attn for the whole row b: A[n][l] = exp(S - M[n]) * Zinv[n]
    {
        const float* Sb = g_S + (size_t)b * NHEAD * LL;
        for (int l = tid; l < LL; l += 256) {
            float s = __expf(Sb[0 * LL + l] - sMg[0]) * sZinv[0]
                    + __expf(Sb[1 * LL + l] - sMg[1]) * sZinv[1]
                    + __expf(Sb[2 * LL + l] - sMg[2]) * sZinv[2]
                    + __expf(Sb[3 * LL + l] - sMg[3]) * sZinv[3];
            outp[BB * HH + (size_t)b * LL + l] = s;
        }
        if (tid == 0) g_cnt[b] = 0;   // reset for next graph replay
    }
}

extern "C" void kernel_launch(void* const* d_in, const int* in_sizes, int n_in,
                              void* d_out, int out_size)
{
    const float* node  = (const float*)d_in[0];
    const float* neigh = (const float*)d_in[1];
    const void*  mask  = d_in[2];
    const int*   step  = (const int*)d_in[3];
    const float* wqs   = (const float*)d_in[4];
    const float* wks   = (const float*)d_in[5];
    const float* wvs   = (const float*)d_in[6];
    const float* prjw  = (const float*)d_in[7];
    const float* prjb  = (const float*)d_in[8];
    const float* gamma = (const float*)d_in[9];
    const float* beta  = (const float*)d_in[10];
    float* outp = (float*)d_out;

    prep_kernel<<<132, 256>>>(node, wqs, wks, wvs, prjw,
                              (const unsigned int*)mask, step);
    mega2_kernel<<<dim3(BB, CH), 256>>>(node, neigh, mask, prjb, gamma, beta,
                                        step, outp);
}